// round 7
// baseline (speedup 1.0000x reference)
#include <cuda_runtime.h>
#include <math.h>
#include <stddef.h>

#define BB     4
#define SS     1024
#define DMODEL 512
#define HH     8
#define DHEAD  64
#define DFF    2048
#define BHTOT  (BB*HH)          // 32
#define MROWS  (BB*SS)          // 4096
#define NCHUNK 64               // softmax partial chunks per (b,h) (8x8 logit blocks)

// ---------------- scratch (static device globals: alloc-free) ----------------
__device__ float g_L[(size_t)BHTOT * SS * SS];   // 128 MB logits
__device__ float g_q[MROWS * DMODEL];
__device__ float g_k[MROWS * DMODEL];
__device__ float g_v[MROWS * DMODEL];
__device__ float g_o[MROWS * DMODEL];
__device__ float g_t0[MROWS * DMODEL];
__device__ float g_out1[MROWS * DMODEL];
__device__ float g_ffn1[MROWS * DFF];
__device__ float g_h[MROWS * DMODEL];
__device__ float g_pm[BHTOT * NCHUNK];
__device__ float g_ps[BHTOT * NCHUNK];
__device__ float g_M[BHTOT];
__device__ float g_scale[BHTOT];
__device__ float g_nz;

// ---------------- helpers ----------------
__device__ __forceinline__ unsigned f2tf(float x) {
    unsigned r; asm("cvt.rna.tf32.f32 %0, %1;" : "=r"(r) : "f"(x)); return r;
}
__device__ __forceinline__ void split_tf(float x, unsigned& hi, unsigned& lo) {
    hi = f2tf(x);
    lo = f2tf(x - __uint_as_float(hi));
}
__device__ __forceinline__ void mma_tf32(float c[4], const unsigned a[4], const unsigned b[2]) {
    asm volatile(
        "mma.sync.aligned.m16n8k8.row.col.f32.tf32.tf32.f32 "
        "{%0,%1,%2,%3}, {%4,%5,%6,%7}, {%8,%9}, {%0,%1,%2,%3};\n"
        : "+f"(c[0]), "+f"(c[1]), "+f"(c[2]), "+f"(c[3])
        : "r"(a[0]), "r"(a[1]), "r"(a[2]), "r"(a[3]), "r"(b[0]), "r"(b[1]));
}

// ---------------- count_nonzero(protok[0]) ----------------
__global__ void count_nz_kernel(const int* __restrict__ protok) {
    __shared__ int cnt[256];
    int t = threadIdx.x;
    int c = 0;
    for (int i = t; i < SS; i += 256) c += (protok[i] != 0);
    cnt[t] = c; __syncthreads();
    for (int off = 128; off; off >>= 1) {
        if (t < off) cnt[t] += cnt[t + off];
        __syncthreads();
    }
    if (t == 0) g_nz = (float)cnt[0];
}

// ---------------- tf32 tensor-core GEMM: C = act(A[4096xK] * B[KxN] + bias) ----------------
// 128x128 tile, BK=32, 256 threads (8 warps, 2x4), warp tile 64x32, m16n8k8.
// blockIdx.z selects one of up to 3 (B, bias, C) sets (fused QKV).
template <bool RELU>
__global__ void __launch_bounds__(256) gemm_tf32(
    const float* __restrict__ A,
    const float* __restrict__ B0, const float* __restrict__ bias0, float* __restrict__ C0,
    const float* __restrict__ B1, const float* __restrict__ bias1, float* __restrict__ C1,
    const float* __restrict__ B2, const float* __restrict__ bias2, float* __restrict__ C2,
    int N, int K)
{
    __shared__ unsigned As[128][36];     // [m][k], bank: (4m+k)%32 bijective
    __shared__ unsigned Bs[32][136];     // [k][n], bank: (8k+n)%32 bijective

    const float* Bm = B0; const float* bias = bias0; float* C = C0;
    if (blockIdx.z == 1) { Bm = B1; bias = bias1; C = C1; }
    else if (blockIdx.z == 2) { Bm = B2; bias = bias2; C = C2; }

    const int tid = threadIdx.x;
    const int wid = tid >> 5, lane = tid & 31;
    const int g = lane >> 2, t4 = lane & 3;
    const int warpM = wid & 1, warpN = wid >> 1;     // 2 x 4
    const int row0 = blockIdx.y * 128;
    const int col0 = blockIdx.x * 128;

    // global load mappings
    const int arow = tid >> 3;           // 0..31 (+i*32)
    const int acol = (tid & 7) * 4;
    const int brow = tid >> 5;           // 0..7 (+i*8)
    const int bcol = (tid & 31) * 4;

    float4 ra[4], rb[4];
    float acc[4][4][4];
    #pragma unroll
    for (int mi = 0; mi < 4; mi++)
        #pragma unroll
        for (int nj = 0; nj < 4; nj++)
            #pragma unroll
            for (int c = 0; c < 4; c++) acc[mi][nj][c] = 0.f;

    auto loadG = [&](int k0) {
        #pragma unroll
        for (int i = 0; i < 4; i++)
            ra[i] = *(const float4*)(A + (size_t)(row0 + arow + i * 32) * K + k0 + acol);
        #pragma unroll
        for (int i = 0; i < 4; i++)
            rb[i] = *(const float4*)(Bm + (size_t)(k0 + brow + i * 8) * N + col0 + bcol);
    };
    auto storeS = [&]() {
        #pragma unroll
        for (int i = 0; i < 4; i++) {
            uint4 u;
            u.x = f2tf(ra[i].x); u.y = f2tf(ra[i].y); u.z = f2tf(ra[i].z); u.w = f2tf(ra[i].w);
            *(uint4*)&As[arow + i * 32][acol] = u;
        }
        #pragma unroll
        for (int i = 0; i < 4; i++) {
            uint4 u;
            u.x = f2tf(rb[i].x); u.y = f2tf(rb[i].y); u.z = f2tf(rb[i].z); u.w = f2tf(rb[i].w);
            *(uint4*)&Bs[brow + i * 8][bcol] = u;
        }
    };

    loadG(0); storeS(); __syncthreads();

    for (int k0 = 0; k0 < K; k0 += 32) {
        const bool more = (k0 + 32) < K;
        if (more) loadG(k0 + 32);
        #pragma unroll
        for (int ks = 0; ks < 4; ks++) {
            const int kb = ks * 8;
            unsigned afr[4][4], bfr[4][2];
            #pragma unroll
            for (int mi = 0; mi < 4; mi++) {
                const int rm = warpM * 64 + mi * 16;
                afr[mi][0] = As[rm + g][kb + t4];
                afr[mi][1] = As[rm + g + 8][kb + t4];
                afr[mi][2] = As[rm + g][kb + t4 + 4];
                afr[mi][3] = As[rm + g + 8][kb + t4 + 4];
            }
            #pragma unroll
            for (int nj = 0; nj < 4; nj++) {
                const int cn = warpN * 32 + nj * 8;
                bfr[nj][0] = Bs[kb + t4][cn + g];
                bfr[nj][1] = Bs[kb + t4 + 4][cn + g];
            }
            #pragma unroll
            for (int mi = 0; mi < 4; mi++)
                #pragma unroll
                for (int nj = 0; nj < 4; nj++)
                    mma_tf32(acc[mi][nj], afr[mi], bfr[nj]);
        }
        __syncthreads();
        if (more) { storeS(); __syncthreads(); }
    }

    // epilogue
    #pragma unroll
    for (int mi = 0; mi < 4; mi++) {
        const int r = row0 + warpM * 64 + mi * 16 + g;
        #pragma unroll
        for (int nj = 0; nj < 4; nj++) {
            const int c = col0 + warpN * 32 + nj * 8 + 2 * t4;
            const float b0 = bias[c], b1 = bias[c + 1];
            float v0 = acc[mi][nj][0] + b0, v1 = acc[mi][nj][1] + b1;
            float v2 = acc[mi][nj][2] + b0, v3 = acc[mi][nj][3] + b1;
            if (RELU) {
                v0 = fmaxf(v0, 0.f); v1 = fmaxf(v1, 0.f);
                v2 = fmaxf(v2, 0.f); v3 = fmaxf(v3, 0.f);
            }
            float2 p0; p0.x = v0; p0.y = v1;
            float2 p1; p1.x = v2; p1.y = v3;
            *(float2*)&C[(size_t)r * N + c] = p0;
            *(float2*)&C[(size_t)(r + 8) * N + c] = p1;
        }
    }
}

// ---------------- logits via 3xTF32 tensor cores (fp32-equivalent precision) ----------------
// L[bh,i,j] = (q_i . k_j)/8 - 1e9*mask[b,i,j].  128x128 tile, BK=16, 8 warps (2x4),
// warp tile 64x32, each product via hi*hi + hi*lo + lo*hi mma.m16n8k8.
// Epilogue: scale, mask, store L, fused per-block (max, sumexp) partial.
__global__ void __launch_bounds__(256) logits_tf32(
    const float* __restrict__ q, const float* __restrict__ kmat,
    const float* __restrict__ mask)
{
    __shared__ unsigned Qh[128][20], Ql[128][20];   // [i][d], bank (4i+d)%32... (20i+d): g-stride 20 -> bijective
    __shared__ unsigned Kh[128][20], Kl[128][20];   // [j][d]
    __shared__ float red_m[256], red_s[256];

    const int bh = blockIdx.z, b = bh >> 3, h = bh & 7;
    const int i0 = blockIdx.y * 128, j0 = blockIdx.x * 128;
    const int tid = threadIdx.x;
    const int wid = tid >> 5, lane = tid & 31;
    const int g = lane >> 2, t4 = lane & 3;
    const int warpM = wid & 1, warpN = wid >> 1;     // 2 x 4

    const float* qb = q + (size_t)(b * SS + i0) * DMODEL + h * 64;
    const float* kb = kmat + (size_t)(b * SS + j0) * DMODEL + h * 64;

    // global load mapping: 64 rows x 16 cols per pass, 2 passes for 128 rows
    const int arow = tid >> 2;           // 0..63 (+64)
    const int acol = (tid & 3) * 4;      // 0,4,8,12

    float4 rq[2], rk[2];
    float acc[4][4][4];
    #pragma unroll
    for (int mi = 0; mi < 4; mi++)
        #pragma unroll
        for (int nj = 0; nj < 4; nj++)
            #pragma unroll
            for (int c = 0; c < 4; c++) acc[mi][nj][c] = 0.f;

    auto loadG = [&](int k0) {
        rq[0] = *(const float4*)(qb + (size_t)arow * DMODEL + k0 + acol);
        rq[1] = *(const float4*)(qb + (size_t)(arow + 64) * DMODEL + k0 + acol);
        rk[0] = *(const float4*)(kb + (size_t)arow * DMODEL + k0 + acol);
        rk[1] = *(const float4*)(kb + (size_t)(arow + 64) * DMODEL + k0 + acol);
    };
    auto storeS = [&]() {
        #pragma unroll
        for (int p = 0; p < 2; p++) {
            const int r = arow + p * 64;
            unsigned h0, l0, h1, l1, h2, l2, h3, l3;
            split_tf(rq[p].x, h0, l0); split_tf(rq[p].y, h1, l1);
            split_tf(rq[p].z, h2, l2); split_tf(rq[p].w, h3, l3);
            Qh[r][acol + 0] = h0; Qh[r][acol + 1] = h1; Qh[r][acol + 2] = h2; Qh[r][acol + 3] = h3;
            Ql[r][acol + 0] = l0; Ql[r][acol + 1] = l1; Ql[r][acol + 2] = l2; Ql[r][acol + 3] = l3;
            split_tf(rk[p].x, h0, l0); split_tf(rk[p].y, h1, l1);
            split_tf(rk[p].z, h2, l2); split_tf(rk[p].w, h3, l3);
            Kh[r][acol + 0] = h0; Kh[r][acol + 1] = h1; Kh[r][acol + 2] = h2; Kh[r][acol + 3] = h3;
            Kl[r][acol + 0] = l0; Kl[r][acol + 1] = l1; Kl[r][acol + 2] = l2; Kl[r][acol + 3] = l3;
        }
    };

    loadG(0); storeS(); __syncthreads();

    for (int k0 = 0; k0 < 64; k0 += 16) {
        const bool more = (k0 + 16) < 64;
        if (more) loadG(k0 + 16);
        #pragma unroll
        for (int ks = 0; ks < 2; ks++) {
            const int kb8 = ks * 8;
            unsigned ah[4][4], al[4][4], bhf[4][2], blf[4][2];
            #pragma unroll
            for (int mi = 0; mi < 4; mi++) {
                const int rm = warpM * 64 + mi * 16;
                ah[mi][0] = Qh[rm + g][kb8 + t4];
                ah[mi][1] = Qh[rm + g + 8][kb8 + t4];
                ah[mi][2] = Qh[rm + g][kb8 + t4 + 4];
                ah[mi][3] = Qh[rm + g + 8][kb8 + t4 + 4];
                al[mi][0] = Ql[rm + g][kb8 + t4];
                al[mi][1] = Ql[rm + g + 8][kb8 + t4];
                al[mi][2] = Ql[rm + g][kb8 + t4 + 4];
                al[mi][3] = Ql[rm + g + 8][kb8 + t4 + 4];
            }
            #pragma unroll
            for (int nj = 0; nj < 4; nj++) {
                const int cn = warpN * 32 + nj * 8;
                bhf[nj][0] = Kh[cn + g][kb8 + t4];
                bhf[nj][1] = Kh[cn + g][kb8 + t4 + 4];
                blf[nj][0] = Kl[cn + g][kb8 + t4];
                blf[nj][1] = Kl[cn + g][kb8 + t4 + 4];
            }
            #pragma unroll
            for (int mi = 0; mi < 4; mi++)
                #pragma unroll
                for (int nj = 0; nj < 4; nj++) {
                    mma_tf32(acc[mi][nj], ah[mi], blf[nj]);   // hi*lo
                    mma_tf32(acc[mi][nj], al[mi], bhf[nj]);   // lo*hi
                    mma_tf32(acc[mi][nj], ah[mi], bhf[nj]);   // hi*hi
                }
        }
        __syncthreads();
        if (more) { storeS(); __syncthreads(); }
    }

    // epilogue: scale, mask, store L, per-thread (max, sumexp)
    float* Lb = g_L + (size_t)bh * SS * SS;
    const float* mrow = mask + (size_t)b * SS * SS;
    float pm = -1e30f;
    #pragma unroll
    for (int mi = 0; mi < 4; mi++) {
        const int r0 = warpM * 64 + mi * 16 + g;
        #pragma unroll
        for (int nj = 0; nj < 4; nj++) {
            const int c = warpN * 32 + nj * 8 + 2 * t4;
            const int i_a = i0 + r0, i_b = i0 + r0 + 8;
            const int j = j0 + c;
            const float2 m0 = *(const float2*)&mrow[(size_t)i_a * SS + j];
            const float2 m1 = *(const float2*)&mrow[(size_t)i_b * SS + j];
            float v0 = acc[mi][nj][0] * 0.125f - 1e9f * m0.x;
            float v1 = acc[mi][nj][1] * 0.125f - 1e9f * m0.y;
            float v2 = acc[mi][nj][2] * 0.125f - 1e9f * m1.x;
            float v3 = acc[mi][nj][3] * 0.125f - 1e9f * m1.y;
            acc[mi][nj][0] = v0; acc[mi][nj][1] = v1;
            acc[mi][nj][2] = v2; acc[mi][nj][3] = v3;
            float2 p0; p0.x = v0; p0.y = v1;
            float2 p1; p1.x = v2; p1.y = v3;
            *(float2*)&Lb[(size_t)i_a * SS + j] = p0;
            *(float2*)&Lb[(size_t)i_b * SS + j] = p1;
            pm = fmaxf(pm, fmaxf(fmaxf(v0, v1), fmaxf(v2, v3)));
        }
    }
    float psum = 0.f;
    #pragma unroll
    for (int mi = 0; mi < 4; mi++)
        #pragma unroll
        for (int nj = 0; nj < 4; nj++)
            #pragma unroll
            for (int c = 0; c < 4; c++)
                psum += __expf(acc[mi][nj][c] - pm);

    red_m[tid] = pm; red_s[tid] = psum; __syncthreads();
    for (int off = 128; off; off >>= 1) {
        if (tid < off) {
            float m2 = red_m[tid + off], s2 = red_s[tid + off];
            float nm = fmaxf(red_m[tid], m2);
            red_s[tid] = red_s[tid] * __expf(red_m[tid] - nm) + s2 * __expf(m2 - nm);
            red_m[tid] = nm;
        }
        __syncthreads();
    }
    if (tid == 0) {
        const int cid = blockIdx.y * 8 + blockIdx.x;
        g_pm[bh * NCHUNK + cid] = red_m[0];
        g_ps[bh * NCHUNK + cid] = red_s[0];
    }
}

// ---------------- softmax final: M[bh], scale[bh] = nz/Z ----------------
__global__ void __launch_bounds__(NCHUNK) softmax_final_kernel() {
    const int bh = blockIdx.x, tid = threadIdx.x;
    __shared__ float sm[NCHUNK], ss[NCHUNK];
    sm[tid] = g_pm[bh * NCHUNK + tid];
    ss[tid] = g_ps[bh * NCHUNK + tid];
    __syncthreads();
    for (int off = NCHUNK / 2; off; off >>= 1) {
        if (tid < off) {
            float m2 = sm[tid + off], s2 = ss[tid + off];
            float nm = fmaxf(sm[tid], m2);
            ss[tid] = ss[tid] * __expf(sm[tid] - nm) + s2 * __expf(m2 - nm);
            sm[tid] = nm;
        }
        __syncthreads();
    }
    if (tid == 0) {
        g_M[bh] = sm[0];
        g_scale[bh] = g_nz / ss[0];
    }
}

// ---------------- attnv (tf32 mma): O[bh,i,d] = sc * sum_j exp(L[j,i]-M) * V[b,j,h,d] ----------------
// Block: 128 i-rows x 64 d-cols, K(j) tiles of 32. 8 warps (2x4), warp tile 64x16.
__global__ void __launch_bounds__(256) attnv_tf32(
    const float* __restrict__ v, float* __restrict__ o)
{
    __shared__ unsigned Ps[32][132];   // [j][i]  (A^T: exactly mma's [k][m])
    __shared__ unsigned Vs[32][72];    // [j][d]

    const int bh = blockIdx.y, b = bh >> 3, h = bh & 7;
    const int i0 = blockIdx.x * 128;
    const float Mb = g_M[bh], sc = g_scale[bh];

    const int tid = threadIdx.x;
    const int wid = tid >> 5, lane = tid & 31;
    const int g = lane >> 2, t4 = lane & 3;
    const int warpM = wid & 1, warpN = wid >> 1;

    const float* Lb = g_L + (size_t)bh * SS * SS;
    const float* vb = v + (size_t)b * SS * DMODEL + h * 64;

    float acc[4][2][4];
    #pragma unroll
    for (int mi = 0; mi < 4; mi++)
        #pragma unroll
        for (int nj = 0; nj < 2; nj++)
            #pragma unroll
            for (int c = 0; c < 4; c++) acc[mi][nj][c] = 0.f;

    const int pr = tid >> 3;          // j row 0..31
    const int pc4 = (tid & 7) * 4;    // i col, + it*32
    float4 rp[4]; float4 rv[2];

    auto loadG = [&](int j0) {
        #pragma unroll
        for (int it = 0; it < 4; it++)
            rp[it] = *(const float4*)(Lb + (size_t)(j0 + pr) * SS + i0 + pc4 + it * 32);
        #pragma unroll
        for (int it = 0; it < 2; it++)
            rv[it] = *(const float4*)(vb + (size_t)(j0 + pr) * DMODEL + pc4 + it * 32);
    };
    auto storeS = [&]() {
        #pragma unroll
        for (int it = 0; it < 4; it++) {
            uint4 u;
            u.x = f2tf(__expf(rp[it].x - Mb));
            u.y = f2tf(__expf(rp[it].y - Mb));
            u.z = f2tf(__expf(rp[it].z - Mb));
            u.w = f2tf(__expf(rp[it].w - Mb));
            *(uint4*)&Ps[pr][pc4 + it * 32] = u;
        }
        #pragma unroll
        for (int it = 0; it < 2; it++) {
            uint4 u;
            u.x = f2tf(rv[it].x); u.y = f2tf(rv[it].y);
            u.z = f2tf(rv[it].z); u.w = f2tf(rv[it].w);
            *(uint4*)&Vs[pr][pc4 + it * 32] = u;
        }
    };

    loadG(0); storeS(); __syncthreads();

    for (int j0 = 0; j0 < SS; j0 += 32) {
        const bool more = (j0 + 32) < SS;
        if (more) loadG(j0 + 32);
        #pragma unroll
        for (int ks = 0; ks < 4; ks++) {
            const int kb = ks * 8;
            unsigned afr[4][4], bfr[2][2];
            #pragma unroll
            for (int mi = 0; mi < 4; mi++) {
                const int rm = warpM * 64 + mi * 16;
                afr[mi][0] = Ps[kb + t4][rm + g];
                afr[mi][1] = Ps[kb + t4][rm + g + 8];
                afr[mi][2] = Ps[kb + t4 + 4][rm + g];
                afr[mi][3] = Ps[kb + t4 + 4][rm + g + 8];
            }
            #pragma unroll
            for (int nj = 0; nj < 2; nj++) {
                const int cn = warpN * 16 + nj * 8;
                bfr[nj][0] = Vs[kb + t4][cn + g];
                bfr[nj][1] = Vs[kb + t4 + 4][cn + g];
            }
            #pragma unroll
            for (int mi = 0; mi < 4; mi++)
                #pragma unroll
                for (int nj = 0; nj < 2; nj++)
                    mma_tf32(acc[mi][nj], afr[mi], bfr[nj]);
        }
        __syncthreads();
        if (more) { storeS(); __syncthreads(); }
    }

    #pragma unroll
    for (int mi = 0; mi < 4; mi++) {
        const int i = i0 + warpM * 64 + mi * 16 + g;
        #pragma unroll
        for (int nj = 0; nj < 2; nj++) {
            const int c = warpN * 16 + nj * 8 + 2 * t4;
            float2 p0; p0.x = acc[mi][nj][0] * sc; p0.y = acc[mi][nj][1] * sc;
            float2 p1; p1.x = acc[mi][nj][2] * sc; p1.y = acc[mi][nj][3] * sc;
            *(float2*)&o[(size_t)(b * SS + i) * DMODEL + h * 64 + c] = p0;
            *(float2*)&o[(size_t)(b * SS + i + 8) * DMODEL + h * 64 + c] = p1;
        }
    }
}

// ---------------- out = LayerNorm(a + r) * gamma + beta ----------------
__global__ void __launch_bounds__(256) add_ln_kernel(
    const float* __restrict__ a, const float* __restrict__ r,
    const float* __restrict__ gam, const float* __restrict__ bet,
    float* __restrict__ o)
{
    __shared__ float red[256];
    const int row = blockIdx.x, t = threadIdx.x;
    const size_t base = (size_t)row * DMODEL;
    float y0 = a[base + t] + r[base + t];
    float y1 = a[base + t + 256] + r[base + t + 256];
    red[t] = y0 + y1; __syncthreads();
    for (int off = 128; off; off >>= 1) {
        if (t < off) red[t] += red[t + off];
        __syncthreads();
    }
    float mean = red[0] * (1.0f / DMODEL);
    __syncthreads();
    float d0 = y0 - mean, d1 = y1 - mean;
    red[t] = d0 * d0 + d1 * d1; __syncthreads();
    for (int off = 128; off; off >>= 1) {
        if (t < off) red[t] += red[t + off];
        __syncthreads();
    }
    float inv = rsqrtf(red[0] * (1.0f / DMODEL) + 1e-9f);
    o[base + t] = d0 * inv * gam[t] + bet[t];
    o[base + t + 256] = d1 * inv * gam[t + 256] + bet[t + 256];
}

// ---------------- host launcher ----------------
extern "C" void kernel_launch(void* const* d_in, const int* in_sizes, int n_in,
                              void* d_out, int out_size)
{
    (void)in_sizes; (void)n_in; (void)out_size;
    const float* x     = (const float*)d_in[0];
    const float* mask  = (const float*)d_in[1];
    const int*   ptk   = (const int*)d_in[2];
    const float* wq    = (const float*)d_in[3];
    const float* bq    = (const float*)d_in[4];
    const float* wk    = (const float*)d_in[5];
    const float* bk    = (const float*)d_in[6];
    const float* wv    = (const float*)d_in[7];
    const float* bv    = (const float*)d_in[8];
    const float* wo    = (const float*)d_in[9];
    const float* bo    = (const float*)d_in[10];
    const float* w1    = (const float*)d_in[11];
    const float* b1    = (const float*)d_in[12];
    const float* w2    = (const float*)d_in[13];
    const float* b2    = (const float*)d_in[14];
    const float* ln1g  = (const float*)d_in[15];
    const float* ln1b  = (const float*)d_in[16];
    const float* ln2g  = (const float*)d_in[17];
    const float* ln2b  = (const float*)d_in[18];
    float* out = (float*)d_out;

    float *q, *k, *v, *o, *t0, *out1, *ffn1, *hbuf;
    cudaGetSymbolAddress((void**)&q,    g_q);
    cudaGetSymbolAddress((void**)&k,    g_k);
    cudaGetSymbolAddress((void**)&v,    g_v);
    cudaGetSymbolAddress((void**)&o,    g_o);
    cudaGetSymbolAddress((void**)&t0,   g_t0);
    cudaGetSymbolAddress((void**)&out1, g_out1);
    cudaGetSymbolAddress((void**)&ffn1, g_ffn1);
    cudaGetSymbolAddress((void**)&hbuf, g_h);

    count_nz_kernel<<<1, 256>>>(ptk);

    const dim3 gqkv(DMODEL / 128, MROWS / 128, 3);   // (4, 32, 3)
    const dim3 g512(DMODEL / 128, MROWS / 128, 1);   // (4, 32)
    const dim3 gff(DFF / 128, MROWS / 128, 1);       // (16, 32)
    const dim3 glog(SS / 128, SS / 128, BHTOT);      // (8, 8, 32)
    const dim3 gav(SS / 128, BHTOT);                 // (8, 32)

    const float* hin = x;
    for (int l = 0; l < 2; l++) {
        float* hout = (l == 1) ? out : hbuf;

        gemm_tf32<false><<<gqkv, 256>>>(hin,
            wq, bq, q,  wk, bk, k,  wv, bv, v,  DMODEL, DMODEL);

        logits_tf32<<<glog, 256>>>(q, k, mask);
        softmax_final_kernel<<<BHTOT, NCHUNK>>>();
        attnv_tf32<<<gav, 256>>>(v, o);

        gemm_tf32<false><<<g512, 256>>>(o,
            wo, bo, t0,  wo, bo, t0,  wo, bo, t0,  DMODEL, DMODEL);
        add_ln_kernel<<<MROWS, 256>>>(hin, t0, ln1g, ln1b, out1);

        gemm_tf32<true><<<gff, 256>>>(out1,
            w1, b1, ffn1,  w1, b1, ffn1,  w1, b1, ffn1,  DFF, DMODEL);
        gemm_tf32<false><<<g512, 256>>>(ffn1,
            w2, b2, t0,  w2, b2, t0,  w2, b2, t0,  DMODEL, DFF);
        add_ln_kernel<<<MROWS, 256>>>(out1, t0, ln2g, ln2b, hout);

        hin = hout;
    }
}

// round 8
// speedup vs baseline: 1.0026x; 1.0026x over previous
#include <cuda_runtime.h>
#include <math.h>
#include <stddef.h>

#define BB     4
#define SS     1024
#define DMODEL 512
#define HH     8
#define DHEAD  64
#define DFF    2048
#define BHTOT  (BB*HH)          // 32
#define MROWS  (BB*SS)          // 4096
#define NCHUNK 64               // logit-max chunks per (b,h) (8x8 blocks)

// ---------------- scratch (static device globals: alloc-free) ----------------
__device__ float g_L[(size_t)BHTOT * SS * SS];   // 128 MB logits
__device__ float g_q[MROWS * DMODEL];
__device__ float g_k[MROWS * DMODEL];
__device__ float g_v[MROWS * DMODEL];
__device__ float g_o[MROWS * DMODEL];
__device__ float g_t0[MROWS * DMODEL];
__device__ float g_out1[MROWS * DMODEL];
__device__ float g_ffn1[MROWS * DFF];
__device__ float g_h[MROWS * DMODEL];
__device__ float g_pm[BHTOT * NCHUNK];
__device__ float g_ps[BHTOT * 8];                // attnv per-block P-sums
__device__ float g_M[BHTOT];
__device__ float g_scale[BHTOT];
__device__ float g_nz;

// ---------------- helpers ----------------
__device__ __forceinline__ unsigned f2tf(float x) {
    unsigned r; asm("cvt.rna.tf32.f32 %0, %1;" : "=r"(r) : "f"(x)); return r;
}
__device__ __forceinline__ void split_tf(float x, unsigned& hi, unsigned& lo) {
    hi = f2tf(x);
    lo = f2tf(x - __uint_as_float(hi));
}
__device__ __forceinline__ void mma_tf32(float c[4], const unsigned a[4], const unsigned b[2]) {
    asm volatile(
        "mma.sync.aligned.m16n8k8.row.col.f32.tf32.tf32.f32 "
        "{%0,%1,%2,%3}, {%4,%5,%6,%7}, {%8,%9}, {%0,%1,%2,%3};\n"
        : "+f"(c[0]), "+f"(c[1]), "+f"(c[2]), "+f"(c[3])
        : "r"(a[0]), "r"(a[1]), "r"(a[2]), "r"(a[3]), "r"(b[0]), "r"(b[1]));
}

// FMA-pipe exp (no MUFU): x <= 0, magic-number rint + deg-5 Taylor of 2^f.
// rel err ~3e-6 on [-80, 0]; returns ~0 below -80.
__device__ __forceinline__ float fast_exp(float x) {
    x = fmaxf(x, -80.f);
    float y = x * 1.442695041f;
    float z = y + 12582912.f;                        // 2^23 + 2^22
    int   n = __float_as_int(z) - 0x4B400000;
    float f = y - (z - 12582912.f);                  // [-0.5, 0.5]
    float p = 1.3333558e-3f;
    p = fmaf(p, f, 9.6181291e-3f);
    p = fmaf(p, f, 5.5504109e-2f);
    p = fmaf(p, f, 2.4022651e-1f);
    p = fmaf(p, f, 6.9314718e-1f);
    p = fmaf(p, f, 1.0f);
    return __int_as_float((n + 127) << 23) * p;
}

// ---------------- count_nonzero(protok[0]) ----------------
__global__ void count_nz_kernel(const int* __restrict__ protok) {
    __shared__ int cnt[256];
    int t = threadIdx.x;
    int c = 0;
    for (int i = t; i < SS; i += 256) c += (protok[i] != 0);
    cnt[t] = c; __syncthreads();
    for (int off = 128; off; off >>= 1) {
        if (t < off) cnt[t] += cnt[t + off];
        __syncthreads();
    }
    if (t == 0) g_nz = (float)cnt[0];
}

// ---------------- tf32 tensor-core GEMM: C = act(scaleA(A)[4096xK] * B[KxN] + bias) ----------------
// 128x128 tile, BK=32, 256 threads (8 warps, 2x4), warp tile 64x32, m16n8k8.
// blockIdx.z selects one of up to 3 (B, bias, C) sets (fused QKV).
// SCALEA: A element (row, k) is multiplied by ascale[(row>>10)*8 + (k>>6)]
// (the deferred global-softmax normalization, constant per tile/k-group).
template <bool RELU, bool SCALEA>
__global__ void __launch_bounds__(256) gemm_tf32(
    const float* __restrict__ A,
    const float* __restrict__ B0, const float* __restrict__ bias0, float* __restrict__ C0,
    const float* __restrict__ B1, const float* __restrict__ bias1, float* __restrict__ C1,
    const float* __restrict__ B2, const float* __restrict__ bias2, float* __restrict__ C2,
    int N, int K, const float* __restrict__ ascale)
{
    __shared__ unsigned As[128][36];     // [m][k]
    __shared__ unsigned Bs[32][136];     // [k][n]

    const float* Bm = B0; const float* bias = bias0; float* C = C0;
    if (blockIdx.z == 1) { Bm = B1; bias = bias1; C = C1; }
    else if (blockIdx.z == 2) { Bm = B2; bias = bias2; C = C2; }

    const int tid = threadIdx.x;
    const int wid = tid >> 5, lane = tid & 31;
    const int g = lane >> 2, t4 = lane & 3;
    const int warpM = wid & 1, warpN = wid >> 1;     // 2 x 4
    const int row0 = blockIdx.y * 128;
    const int col0 = blockIdx.x * 128;

    const int arow = tid >> 3;           // 0..31 (+i*32)
    const int acol = (tid & 7) * 4;
    const int brow = tid >> 5;           // 0..7 (+i*8)
    const int bcol = (tid & 31) * 4;

    float4 ra[4], rb[4];
    float acc[4][4][4];
    #pragma unroll
    for (int mi = 0; mi < 4; mi++)
        #pragma unroll
        for (int nj = 0; nj < 4; nj++)
            #pragma unroll
            for (int c = 0; c < 4; c++) acc[mi][nj][c] = 0.f;

    auto loadG = [&](int k0) {
        #pragma unroll
        for (int i = 0; i < 4; i++)
            ra[i] = *(const float4*)(A + (size_t)(row0 + arow + i * 32) * K + k0 + acol);
        if (SCALEA) {
            const float s = ascale[((row0 >> 10) << 3) + ((k0 + acol) >> 6)];
            #pragma unroll
            for (int i = 0; i < 4; i++) {
                ra[i].x *= s; ra[i].y *= s; ra[i].z *= s; ra[i].w *= s;
            }
        }
        #pragma unroll
        for (int i = 0; i < 4; i++)
            rb[i] = *(const float4*)(Bm + (size_t)(k0 + brow + i * 8) * N + col0 + bcol);
    };
    auto storeS = [&]() {
        #pragma unroll
        for (int i = 0; i < 4; i++) {
            uint4 u;
            u.x = f2tf(ra[i].x); u.y = f2tf(ra[i].y); u.z = f2tf(ra[i].z); u.w = f2tf(ra[i].w);
            *(uint4*)&As[arow + i * 32][acol] = u;
        }
        #pragma unroll
        for (int i = 0; i < 4; i++) {
            uint4 u;
            u.x = f2tf(rb[i].x); u.y = f2tf(rb[i].y); u.z = f2tf(rb[i].z); u.w = f2tf(rb[i].w);
            *(uint4*)&Bs[brow + i * 8][bcol] = u;
        }
    };

    loadG(0); storeS(); __syncthreads();

    for (int k0 = 0; k0 < K; k0 += 32) {
        const bool more = (k0 + 32) < K;
        if (more) loadG(k0 + 32);
        #pragma unroll
        for (int ks = 0; ks < 4; ks++) {
            const int kb = ks * 8;
            unsigned afr[4][4], bfr[4][2];
            #pragma unroll
            for (int mi = 0; mi < 4; mi++) {
                const int rm = warpM * 64 + mi * 16;
                afr[mi][0] = As[rm + g][kb + t4];
                afr[mi][1] = As[rm + g + 8][kb + t4];
                afr[mi][2] = As[rm + g][kb + t4 + 4];
                afr[mi][3] = As[rm + g + 8][kb + t4 + 4];
            }
            #pragma unroll
            for (int nj = 0; nj < 4; nj++) {
                const int cn = warpN * 32 + nj * 8;
                bfr[nj][0] = Bs[kb + t4][cn + g];
                bfr[nj][1] = Bs[kb + t4 + 4][cn + g];
            }
            #pragma unroll
            for (int mi = 0; mi < 4; mi++)
                #pragma unroll
                for (int nj = 0; nj < 4; nj++)
                    mma_tf32(acc[mi][nj], afr[mi], bfr[nj]);
        }
        __syncthreads();
        if (more) { storeS(); __syncthreads(); }
    }

    #pragma unroll
    for (int mi = 0; mi < 4; mi++) {
        const int r = row0 + warpM * 64 + mi * 16 + g;
        #pragma unroll
        for (int nj = 0; nj < 4; nj++) {
            const int c = col0 + warpN * 32 + nj * 8 + 2 * t4;
            const float b0 = bias[c], b1 = bias[c + 1];
            float v0 = acc[mi][nj][0] + b0, v1 = acc[mi][nj][1] + b1;
            float v2 = acc[mi][nj][2] + b0, v3 = acc[mi][nj][3] + b1;
            if (RELU) {
                v0 = fmaxf(v0, 0.f); v1 = fmaxf(v1, 0.f);
                v2 = fmaxf(v2, 0.f); v3 = fmaxf(v3, 0.f);
            }
            float2 p0; p0.x = v0; p0.y = v1;
            float2 p1; p1.x = v2; p1.y = v3;
            *(float2*)&C[(size_t)r * N + c] = p0;
            *(float2*)&C[(size_t)(r + 8) * N + c] = p1;
        }
    }
}

// ---------------- logits via 3xTF32 tensor cores (fp32-equivalent precision) ----------------
// L[bh,i,j] = (q_i . k_j)/8 - 1e9*mask[b,i,j].  128x128 tile, BK=16, 8 warps (2x4),
// warp tile 64x32, each product via hi*hi + hi*lo + lo*hi mma.m16n8k8.
// Epilogue: scale, mask, store L, fused per-block MAX partial (no exp here).
__global__ void __launch_bounds__(256) logits_tf32(
    const float* __restrict__ q, const float* __restrict__ kmat,
    const float* __restrict__ mask)
{
    __shared__ unsigned Qh[128][20], Ql[128][20];   // [i][d]
    __shared__ unsigned Kh[128][20], Kl[128][20];   // [j][d]
    __shared__ float red_m[256];

    const int bh = blockIdx.z, b = bh >> 3, h = bh & 7;
    const int i0 = blockIdx.y * 128, j0 = blockIdx.x * 128;
    const int tid = threadIdx.x;
    const int wid = tid >> 5, lane = tid & 31;
    const int g = lane >> 2, t4 = lane & 3;
    const int warpM = wid & 1, warpN = wid >> 1;     // 2 x 4

    const float* qb = q + (size_t)(b * SS + i0) * DMODEL + h * 64;
    const float* kb = kmat + (size_t)(b * SS + j0) * DMODEL + h * 64;

    const int arow = tid >> 2;           // 0..63 (+64)
    const int acol = (tid & 3) * 4;      // 0,4,8,12

    float4 rq[2], rk[2];
    float acc[4][4][4];
    #pragma unroll
    for (int mi = 0; mi < 4; mi++)
        #pragma unroll
        for (int nj = 0; nj < 4; nj++)
            #pragma unroll
            for (int c = 0; c < 4; c++) acc[mi][nj][c] = 0.f;

    auto loadG = [&](int k0) {
        rq[0] = *(const float4*)(qb + (size_t)arow * DMODEL + k0 + acol);
        rq[1] = *(const float4*)(qb + (size_t)(arow + 64) * DMODEL + k0 + acol);
        rk[0] = *(const float4*)(kb + (size_t)arow * DMODEL + k0 + acol);
        rk[1] = *(const float4*)(kb + (size_t)(arow + 64) * DMODEL + k0 + acol);
    };
    auto storeS = [&]() {
        #pragma unroll
        for (int p = 0; p < 2; p++) {
            const int r = arow + p * 64;
            unsigned h0, l0, h1, l1, h2, l2, h3, l3;
            split_tf(rq[p].x, h0, l0); split_tf(rq[p].y, h1, l1);
            split_tf(rq[p].z, h2, l2); split_tf(rq[p].w, h3, l3);
            Qh[r][acol + 0] = h0; Qh[r][acol + 1] = h1; Qh[r][acol + 2] = h2; Qh[r][acol + 3] = h3;
            Ql[r][acol + 0] = l0; Ql[r][acol + 1] = l1; Ql[r][acol + 2] = l2; Ql[r][acol + 3] = l3;
            split_tf(rk[p].x, h0, l0); split_tf(rk[p].y, h1, l1);
            split_tf(rk[p].z, h2, l2); split_tf(rk[p].w, h3, l3);
            Kh[r][acol + 0] = h0; Kh[r][acol + 1] = h1; Kh[r][acol + 2] = h2; Kh[r][acol + 3] = h3;
            Kl[r][acol + 0] = l0; Kl[r][acol + 1] = l1; Kl[r][acol + 2] = l2; Kl[r][acol + 3] = l3;
        }
    };

    loadG(0); storeS(); __syncthreads();

    for (int k0 = 0; k0 < 64; k0 += 16) {
        const bool more = (k0 + 16) < 64;
        if (more) loadG(k0 + 16);
        #pragma unroll
        for (int ks = 0; ks < 2; ks++) {
            const int kb8 = ks * 8;
            unsigned ah[4][4], al[4][4], bhf[4][2], blf[4][2];
            #pragma unroll
            for (int mi = 0; mi < 4; mi++) {
                const int rm = warpM * 64 + mi * 16;
                ah[mi][0] = Qh[rm + g][kb8 + t4];
                ah[mi][1] = Qh[rm + g + 8][kb8 + t4];
                ah[mi][2] = Qh[rm + g][kb8 + t4 + 4];
                ah[mi][3] = Qh[rm + g + 8][kb8 + t4 + 4];
                al[mi][0] = Ql[rm + g][kb8 + t4];
                al[mi][1] = Ql[rm + g + 8][kb8 + t4];
                al[mi][2] = Ql[rm + g][kb8 + t4 + 4];
                al[mi][3] = Ql[rm + g + 8][kb8 + t4 + 4];
            }
            #pragma unroll
            for (int nj = 0; nj < 4; nj++) {
                const int cn = warpN * 32 + nj * 8;
                bhf[nj][0] = Kh[cn + g][kb8 + t4];
                bhf[nj][1] = Kh[cn + g][kb8 + t4 + 4];
                blf[nj][0] = Kl[cn + g][kb8 + t4];
                blf[nj][1] = Kl[cn + g][kb8 + t4 + 4];
            }
            #pragma unroll
            for (int mi = 0; mi < 4; mi++)
                #pragma unroll
                for (int nj = 0; nj < 4; nj++) {
                    mma_tf32(acc[mi][nj], ah[mi], blf[nj]);   // hi*lo
                    mma_tf32(acc[mi][nj], al[mi], bhf[nj]);   // lo*hi
                    mma_tf32(acc[mi][nj], ah[mi], bhf[nj]);   // hi*hi
                }
        }
        __syncthreads();
        if (more) { storeS(); __syncthreads(); }
    }

    // epilogue: scale, mask, store L, per-thread max (NO exp)
    float* Lb = g_L + (size_t)bh * SS * SS;
    const float* mrow = mask + (size_t)b * SS * SS;
    float pm = -1e30f;
    #pragma unroll
    for (int mi = 0; mi < 4; mi++) {
        const int r0 = warpM * 64 + mi * 16 + g;
        #pragma unroll
        for (int nj = 0; nj < 4; nj++) {
            const int c = warpN * 32 + nj * 8 + 2 * t4;
            const int i_a = i0 + r0, i_b = i0 + r0 + 8;
            const int j = j0 + c;
            const float2 m0 = *(const float2*)&mrow[(size_t)i_a * SS + j];
            const float2 m1 = *(const float2*)&mrow[(size_t)i_b * SS + j];
            float v0 = acc[mi][nj][0] * 0.125f - 1e9f * m0.x;
            float v1 = acc[mi][nj][1] * 0.125f - 1e9f * m0.y;
            float v2 = acc[mi][nj][2] * 0.125f - 1e9f * m1.x;
            float v3 = acc[mi][nj][3] * 0.125f - 1e9f * m1.y;
            float2 p0; p0.x = v0; p0.y = v1;
            float2 p1; p1.x = v2; p1.y = v3;
            *(float2*)&Lb[(size_t)i_a * SS + j] = p0;
            *(float2*)&Lb[(size_t)i_b * SS + j] = p1;
            pm = fmaxf(pm, fmaxf(fmaxf(v0, v1), fmaxf(v2, v3)));
        }
    }

    red_m[tid] = pm; __syncthreads();
    for (int off = 128; off; off >>= 1) {
        if (tid < off) red_m[tid] = fmaxf(red_m[tid], red_m[tid + off]);
        __syncthreads();
    }
    if (tid == 0) {
        const int cid = blockIdx.y * 8 + blockIdx.x;
        g_pm[bh * NCHUNK + cid] = red_m[0];
    }
}

// ---------------- max final: M[bh] = max over chunks ----------------
__global__ void __launch_bounds__(NCHUNK) max_final_kernel() {
    const int bh = blockIdx.x, tid = threadIdx.x;
    __shared__ float sm[NCHUNK];
    sm[tid] = g_pm[bh * NCHUNK + tid];
    __syncthreads();
    for (int off = NCHUNK / 2; off; off >>= 1) {
        if (tid < off) sm[tid] = fmaxf(sm[tid], sm[tid + off]);
        __syncthreads();
    }
    if (tid == 0) g_M[bh] = sm[0];
}

// ---------------- attnv (tf32 mma): Ou[bh,i,d] = sum_j exp(L[j,i]-M) * V[b,j,h,d] ----------------
// Also accumulates the per-block sum of exp(L-M) into g_ps (for the global Z).
// Output is UNSCALED; the nz/Z scale is applied in the wo GEMM's A-load.
__global__ void __launch_bounds__(256) attnv_tf32(
    const float* __restrict__ v, float* __restrict__ o)
{
    __shared__ unsigned Ps[32][132];   // [j][i]
    __shared__ unsigned Vs[32][72];    // [j][d]
    __shared__ float red[256];

    const int bh = blockIdx.y, b = bh >> 3, h = bh & 7;
    const int i0 = blockIdx.x * 128;
    const float Mb = g_M[bh];

    const int tid = threadIdx.x;
    const int wid = tid >> 5, lane = tid & 31;
    const int g = lane >> 2, t4 = lane & 3;
    const int warpM = wid & 1, warpN = wid >> 1;

    const float* Lb = g_L + (size_t)bh * SS * SS;
    const float* vb = v + (size_t)b * SS * DMODEL + h * 64;

    float acc[4][2][4];
    #pragma unroll
    for (int mi = 0; mi < 4; mi++)
        #pragma unroll
        for (int nj = 0; nj < 2; nj++)
            #pragma unroll
            for (int c = 0; c < 4; c++) acc[mi][nj][c] = 0.f;

    const int pr = tid >> 3;          // j row 0..31
    const int pc4 = (tid & 7) * 4;    // i col, + it*32
    float4 rp[4]; float4 rv[2];
    float psum = 0.f;

    auto loadG = [&](int j0) {
        #pragma unroll
        for (int it = 0; it < 4; it++)
            rp[it] = *(const float4*)(Lb + (size_t)(j0 + pr) * SS + i0 + pc4 + it * 32);
        #pragma unroll
        for (int it = 0; it < 2; it++)
            rv[it] = *(const float4*)(vb + (size_t)(j0 + pr) * DMODEL + pc4 + it * 32);
    };
    auto storeS = [&]() {
        #pragma unroll
        for (int it = 0; it < 4; it++) {
            float e0 = fast_exp(rp[it].x - Mb);
            float e1 = fast_exp(rp[it].y - Mb);
            float e2 = fast_exp(rp[it].z - Mb);
            float e3 = fast_exp(rp[it].w - Mb);
            psum += (e0 + e1) + (e2 + e3);
            uint4 u;
            u.x = f2tf(e0); u.y = f2tf(e1); u.z = f2tf(e2); u.w = f2tf(e3);
            *(uint4*)&Ps[pr][pc4 + it * 32] = u;
        }
        #pragma unroll
        for (int it = 0; it < 2; it++) {
            uint4 u;
            u.x = f2tf(rv[it].x); u.y = f2tf(rv[it].y);
            u.z = f2tf(rv[it].z); u.w = f2tf(rv[it].w);
            *(uint4*)&Vs[pr][pc4 + it * 32] = u;
        }
    };

    loadG(0); storeS(); __syncthreads();

    for (int j0 = 0; j0 < SS; j0 += 32) {
        const bool more = (j0 + 32) < SS;
        if (more) loadG(j0 + 32);
        #pragma unroll
        for (int ks = 0; ks < 4; ks++) {
            const int kb = ks * 8;
            unsigned afr[4][4], bfr[2][2];
            #pragma unroll
            for (int mi = 0; mi < 4; mi++) {
                const int rm = warpM * 64 + mi * 16;
                afr[mi][0] = Ps[kb + t4][rm + g];
                afr[mi][1] = Ps[kb + t4][rm + g + 8];
                afr[mi][2] = Ps[kb + t4 + 4][rm + g];
                afr[mi][3] = Ps[kb + t4 + 4][rm + g + 8];
            }
            #pragma unroll
            for (int nj = 0; nj < 2; nj++) {
                const int cn = warpN * 16 + nj * 8;
                bfr[nj][0] = Vs[kb + t4][cn + g];
                bfr[nj][1] = Vs[kb + t4 + 4][cn + g];
            }
            #pragma unroll
            for (int mi = 0; mi < 4; mi++)
                #pragma unroll
                for (int nj = 0; nj < 2; nj++)
                    mma_tf32(acc[mi][nj], afr[mi], bfr[nj]);
        }
        __syncthreads();
        if (more) { storeS(); __syncthreads(); }
    }

    // reduce the block's P-sum (partial of Z)
    red[tid] = psum; __syncthreads();
    for (int off = 128; off; off >>= 1) {
        if (tid < off) red[tid] += red[tid + off];
        __syncthreads();
    }
    if (tid == 0) g_ps[bh * 8 + blockIdx.x] = red[0];

    #pragma unroll
    for (int mi = 0; mi < 4; mi++) {
        const int i = i0 + warpM * 64 + mi * 16 + g;
        #pragma unroll
        for (int nj = 0; nj < 2; nj++) {
            const int c = warpN * 16 + nj * 8 + 2 * t4;
            float2 p0; p0.x = acc[mi][nj][0]; p0.y = acc[mi][nj][1];
            float2 p1; p1.x = acc[mi][nj][2]; p1.y = acc[mi][nj][3];
            *(float2*)&o[(size_t)(b * SS + i) * DMODEL + h * 64 + c] = p0;
            *(float2*)&o[(size_t)(b * SS + i + 8) * DMODEL + h * 64 + c] = p1;
        }
    }
}

// ---------------- scale final: g_scale[bh] = nz / Z ----------------
__global__ void __launch_bounds__(32) scale_final_kernel() {
    const int bh = blockIdx.x;
    const int lane = threadIdx.x;
    float s = (lane < 8) ? g_ps[bh * 8 + lane] : 0.f;
    #pragma unroll
    for (int off = 4; off; off >>= 1)
        s += __shfl_down_sync(0xFFFFFFFF, s, off);
    if (lane == 0) g_scale[bh] = g_nz / s;
}

// ---------------- out = LayerNorm(a + r) * gamma + beta ----------------
__global__ void __launch_bounds__(256) add_ln_kernel(
    const float* __restrict__ a, const float* __restrict__ r,
    const float* __restrict__ gam, const float* __restrict__ bet,
    float* __restrict__ o)
{
    __shared__ float red[256];
    const int row = blockIdx.x, t = threadIdx.x;
    const size_t base = (size_t)row * DMODEL;
    float y0 = a[base + t] + r[base + t];
    float y1 = a[base + t + 256] + r[base + t + 256];
    red[t] = y0 + y1; __syncthreads();
    for (int off = 128; off; off >>= 1) {
        if (t < off) red[t] += red[t + off];
        __syncthreads();
    }
    float mean = red[0] * (1.0f / DMODEL);
    __syncthreads();
    float d0 = y0 - mean, d1 = y1 - mean;
    red[t] = d0 * d0 + d1 * d1; __syncthreads();
    for (int off = 128; off; off >>= 1) {
        if (t < off) red[t] += red[t + off];
        __syncthreads();
    }
    float inv = rsqrtf(red[0] * (1.0f / DMODEL) + 1e-9f);
    o[base + t] = d0 * inv * gam[t] + bet[t];
    o[base + t + 256] = d1 * inv * gam[t + 256] + bet[t + 256];
}

// ---------------- host launcher ----------------
extern "C" void kernel_launch(void* const* d_in, const int* in_sizes, int n_in,
                              void* d_out, int out_size)
{
    (void)in_sizes; (void)n_in; (void)out_size;
    const float* x     = (const float*)d_in[0];
    const float* mask  = (const float*)d_in[1];
    const int*   ptk   = (const int*)d_in[2];
    const float* wq    = (const float*)d_in[3];
    const float* bq    = (const float*)d_in[4];
    const float* wk    = (const float*)d_in[5];
    const float* bk    = (const float*)d_in[6];
    const float* wv    = (const float*)d_in[7];
    const float* bv    = (const float*)d_in[8];
    const float* wo    = (const float*)d_in[9];
    const float* bo    = (const float*)d_in[10];
    const float* w1    = (const float*)d_in[11];
    const float* b1    = (const float*)d_in[12];
    const float* w2    = (const float*)d_in[13];
    const float* b2    = (const float*)d_in[14];
    const float* ln1g  = (const float*)d_in[15];
    const float* ln1b  = (const float*)d_in[16];
    const float* ln2g  = (const float*)d_in[17];
    const float* ln2b  = (const float*)d_in[18];
    float* out = (float*)d_out;

    float *q, *k, *v, *o, *t0, *out1, *ffn1, *hbuf, *scl;
    cudaGetSymbolAddress((void**)&q,    g_q);
    cudaGetSymbolAddress((void**)&k,    g_k);
    cudaGetSymbolAddress((void**)&v,    g_v);
    cudaGetSymbolAddress((void**)&o,    g_o);
    cudaGetSymbolAddress((void**)&t0,   g_t0);
    cudaGetSymbolAddress((void**)&out1, g_out1);
    cudaGetSymbolAddress((void**)&ffn1, g_ffn1);
    cudaGetSymbolAddress((void**)&hbuf, g_h);
    cudaGetSymbolAddress((void**)&scl,  g_scale);

    count_nz_kernel<<<1, 256>>>(ptk);

    const dim3 gqkv(DMODEL / 128, MROWS / 128, 3);   // (4, 32, 3)
    const dim3 g512(DMODEL / 128, MROWS / 128, 1);   // (4, 32)
    const dim3 gff(DFF / 128, MROWS / 128, 1);       // (16, 32)
    const dim3 glog(SS / 128, SS / 128, BHTOT);      // (8, 8, 32)
    const dim3 gav(SS / 128, BHTOT);                 // (8, 32)

    const float* hin = x;
    for (int l = 0; l < 2; l++) {
        float* hout = (l == 1) ? out : hbuf;

        gemm_tf32<false, false><<<gqkv, 256>>>(hin,
            wq, bq, q,  wk, bk, k,  wv, bv, v,  DMODEL, DMODEL, nullptr);

        logits_tf32<<<glog, 256>>>(q, k, mask);
        max_final_kernel<<<BHTOT, NCHUNK>>>();
        attnv_tf32<<<gav, 256>>>(v, o);
        scale_final_kernel<<<BHTOT, 32>>>();

        gemm_tf32<false, true><<<g512, 256>>>(o,
            wo, bo, t0,  wo, bo, t0,  wo, bo, t0,  DMODEL, DMODEL, scl);
        add_ln_kernel<<<MROWS, 256>>>(hin, t0, ln1g, ln1b, out1);

        gemm_tf32<true, false><<<gff, 256>>>(out1,
            w1, b1, ffn1,  w1, b1, ffn1,  w1, b1, ffn1,  DFF, DMODEL, nullptr);
        gemm_tf32<false, false><<<g512, 256>>>(ffn1,
            w2, b2, t0,  w2, b2, t0,  w2, b2, t0,  DMODEL, DFF, nullptr);
        add_ln_kernel<<<MROWS, 256>>>(out1, t0, ln2g, ln2b, hout);

        hin = hout;
    }
}